// round 1
// baseline (speedup 1.0000x reference)
#include <cuda_runtime.h>
#include <math.h>
#include <stdint.h>

#define T_STEPS 101
#define INSZ 700
#define H 512
#define OUTSZ 20
#define NBATCH 512
#define THRESH 0.5f
#define DECAY 0.5f
#define CO2 0.02f

// ------------ device scratch (static: no allocs allowed) ------------
__device__ float g_X1[(size_t)T_STEPS * NBATCH * H];   // 106 MB: precomputed input proj (+b1+br)
__device__ float g_WrT[H * H];                         // w_h2h1 transposed (j-major)
__device__ float g_W2T[H * H];                         // w_i2h2 transposed (j-major)
__device__ float g_WoT[H * OUTSZ];                     // w_h2o3 transposed (j-major)
__device__ float g_ce[T_STEPS * H];                    // temporal encoding

// ------------ ce precompute ------------
__global__ void k_ce(const float* __restrict__ fre) {
    int i = threadIdx.x;     // 0..511
    int t = blockIdx.x;      // 0..100
    double dt_d = 0.1 / pow(100.0, (double)i / 512.0);
    float dtf = (float)dt_d;
    float fd  = fre[i] * dtf;          // fp32, matches (fre*dt) in reference
    float arg = fd * (float)t;         // fp32 product, matches broadcast multiply
    g_ce[t * H + i] = (float)cos((double)arg) * 0.1f;
}

// ------------ 512x512 transpose (dst[j][i] = src[i][j]) ------------
__global__ void k_transpose(const float* __restrict__ src, int which) {
    __shared__ float tile[32][33];
    float* dst = (which == 0) ? g_WrT : g_W2T;
    int x  = blockIdx.x * 32 + threadIdx.x;
    int y0 = blockIdx.y * 32;
    for (int r = threadIdx.y; r < 32; r += 8)
        tile[r][threadIdx.x] = src[(size_t)(y0 + r) * H + x];
    __syncthreads();
    int xo  = blockIdx.y * 32 + threadIdx.x;
    int yo0 = blockIdx.x * 32;
    for (int r = threadIdx.y; r < 32; r += 8)
        dst[(size_t)(yo0 + r) * H + xo] = tile[threadIdx.x][r];
}

// ------------ small transpose for readout weights ------------
__global__ void k_wo(const float* __restrict__ wo) {
    int j = threadIdx.x; // 0..511
    for (int k = 0; k < OUTSZ; k++)
        g_WoT[j * OUTSZ + k] = wo[k * H + j];
}

// ------------ X1 GEMM: C[m][n] = sum_k A[m][k]*B[n][k] + b1[n] + br[n] ------------
#define BM 128
#define BN 64
#define BK 16
__global__ __launch_bounds__(256) void k_gemm_x1(
    const float* __restrict__ A,   // input  [51712 x 700]
    const float* __restrict__ B,   // w_i2h1 [512 x 700]
    const float* __restrict__ b1,
    const float* __restrict__ br)
{
    __shared__ float As[BK][BM + 4];
    __shared__ float Bs[BK][BN + 4];
    int tid = threadIdx.x;
    int m0 = blockIdx.y * BM, n0 = blockIdx.x * BN;
    int tr = tid >> 4, tc = tid & 15;  // 16x16 thread grid
    float acc[8][4];
    #pragma unroll
    for (int i = 0; i < 8; i++)
        #pragma unroll
        for (int j = 0; j < 4; j++) acc[i][j] = 0.f;

    for (int k0 = 0; k0 < INSZ; k0 += BK) {
        // load A tile: 128x16 = 512 float4, 2 per thread
        #pragma unroll
        for (int i = 0; i < 2; i++) {
            int idx = tid + i * 256;
            int row = idx >> 2;
            int c4  = (idx & 3) * 4;
            int gk  = k0 + c4;
            float4 v;
            if (gk + 3 < INSZ) {
                v = *(const float4*)&A[(size_t)(m0 + row) * INSZ + gk];
            } else {
                const float* ap = &A[(size_t)(m0 + row) * INSZ];
                v.x = (gk + 0 < INSZ) ? ap[gk + 0] : 0.f;
                v.y = (gk + 1 < INSZ) ? ap[gk + 1] : 0.f;
                v.z = (gk + 2 < INSZ) ? ap[gk + 2] : 0.f;
                v.w = (gk + 3 < INSZ) ? ap[gk + 3] : 0.f;
            }
            As[c4 + 0][row] = v.x; As[c4 + 1][row] = v.y;
            As[c4 + 2][row] = v.z; As[c4 + 3][row] = v.w;
        }
        // load B tile: 64x16 = 256 float4, 1 per thread
        {
            int idx = tid;
            int row = idx >> 2;
            int c4  = (idx & 3) * 4;
            int gk  = k0 + c4;
            float4 v;
            if (gk + 3 < INSZ) {
                v = *(const float4*)&B[(size_t)(n0 + row) * INSZ + gk];
            } else {
                const float* bp = &B[(size_t)(n0 + row) * INSZ];
                v.x = (gk + 0 < INSZ) ? bp[gk + 0] : 0.f;
                v.y = (gk + 1 < INSZ) ? bp[gk + 1] : 0.f;
                v.z = (gk + 2 < INSZ) ? bp[gk + 2] : 0.f;
                v.w = (gk + 3 < INSZ) ? bp[gk + 3] : 0.f;
            }
            Bs[c4 + 0][row] = v.x; Bs[c4 + 1][row] = v.y;
            Bs[c4 + 2][row] = v.z; Bs[c4 + 3][row] = v.w;
        }
        __syncthreads();
        #pragma unroll
        for (int k = 0; k < BK; k++) {
            float a[8], bb[4];
            #pragma unroll
            for (int i = 0; i < 8; i++) a[i] = As[k][tr * 8 + i];
            #pragma unroll
            for (int j = 0; j < 4; j++) bb[j] = Bs[k][tc * 4 + j];
            #pragma unroll
            for (int i = 0; i < 8; i++)
                #pragma unroll
                for (int j = 0; j < 4; j++) acc[i][j] += a[i] * bb[j];
        }
        __syncthreads();
    }
    #pragma unroll
    for (int i = 0; i < 8; i++) {
        int m = m0 + tr * 8 + i;
        #pragma unroll
        for (int j = 0; j < 4; j++) {
            int n = n0 + tc * 4 + j;
            g_X1[(size_t)m * H + n] = acc[i][j] + b1[n] + br[n];
        }
    }
}

// ------------ active-list compaction: union of 4 sample masks -> (j | gmask<<16) ------------
__device__ __forceinline__ void build_list(unsigned (*msk)[16], unsigned* lst, int* cnt, int tid) {
    if (tid < 32) {
        unsigned u = 0, g0 = 0, g1 = 0, g2 = 0, g3 = 0;
        if (tid < 16) {
            g0 = msk[0][tid]; g1 = msk[1][tid]; g2 = msk[2][tid]; g3 = msk[3][tid];
            u = g0 | g1 | g2 | g3;
        }
        int c = __popc(u);
        int off = c;
        #pragma unroll
        for (int d = 1; d < 32; d <<= 1) {
            int v = __shfl_up_sync(0xffffffffu, off, d);
            if (tid >= d) off += v;
        }
        off -= c;                    // exclusive prefix
        if (tid == 31) *cnt = off;   // lane31 has c=0 -> exclusive == total
        unsigned uu = u;
        while (uu) {
            int b = __ffs(uu) - 1;
            uu &= uu - 1;
            unsigned gm = ((g0 >> b) & 1u) | (((g1 >> b) & 1u) << 1)
                        | (((g2 >> b) & 1u) << 2) | (((g3 >> b) & 1u) << 3);
            lst[off++] = (unsigned)(tid * 32 + b) | (gm << 16);
        }
    }
}

// ------------ sequential SNN: 128 CTAs x 4 samples, 256 threads, 2 neurons/thread ------------
__global__ __launch_bounds__(256) void k_snn(
    const float* __restrict__ b2,
    const float* __restrict__ bo,
    float* __restrict__ out)
{
    int tid = threadIdx.x;
    int n0  = blockIdx.x * 4;

    __shared__ unsigned sp1m[4][16];
    __shared__ unsigned sp2m[4][16];
    __shared__ unsigned lst[512];
    __shared__ int s_cnt;

    float mem1[4][2], th1[4][2], mem2[4][2], th2[4][2];
    #pragma unroll
    for (int g = 0; g < 4; g++) {
        mem1[g][0] = mem1[g][1] = 0.f;
        mem2[g][0] = mem2[g][1] = 0.f;
        th1[g][0] = th1[g][1] = THRESH;
        th2[g][0] = th2[g][1] = THRESH;
    }
    unsigned sp1bits = 0, sp2bits = 0; // bit (2g+slot)
    float oacc = 0.f;
    int og = tid / OUTSZ, ok = tid % OUTSZ;
    bool odo = (tid < 4 * OUTSZ);

    if (tid < 16) {
        #pragma unroll
        for (int g = 0; g < 4; g++) { sp1m[g][tid] = 0u; sp2m[g][tid] = 0u; }
    }
    __syncthreads();

    float bias2a = b2[tid], bias2b = b2[tid + 256];

    for (int t = 0; t < T_STEPS; t++) {
        // ================= layer 1 =================
        build_list(sp1m, lst, &s_cnt, tid);
        __syncthreads();
        int cnt = s_cnt;
        float acc0[4] = {0.f, 0.f, 0.f, 0.f};
        float acc1[4] = {0.f, 0.f, 0.f, 0.f};
        #pragma unroll 2
        for (int a = 0; a < cnt; a++) {
            unsigned e = lst[a];
            int j = (int)(e & 0xffffu);
            unsigned gm = e >> 16;
            const float* wr = &g_WrT[(size_t)j * H];
            float w0 = wr[tid], w1 = wr[tid + 256];
            #pragma unroll
            for (int g = 0; g < 4; g++)
                if (gm & (1u << g)) { acc0[g] += w0; acc1[g] += w1; }
        }
        float c0 = g_ce[t * H + tid], c1 = g_ce[t * H + tid + 256];
        unsigned newsp1 = 0;
        #pragma unroll
        for (int g = 0; g < 4; g++) {
            const float* xr = &g_X1[((size_t)t * NBATCH + n0 + g) * H];
            float h0 = xr[tid] + acc0[g];
            float h1v = xr[tid + 256] + acc1[g];
            // slot 0
            th1[g][0] = (th1[g][0] + mem1[g][0] * c0) - (th1[g][0] - THRESH) * CO2;
            float dk0 = ((sp1bits >> (2 * g)) & 1u) ? 0.f : DECAY;
            mem1[g][0] = mem1[g][0] * dk0 + h0;
            if (mem1[g][0] > th1[g][0]) newsp1 |= 1u << (2 * g);
            // slot 1
            th1[g][1] = (th1[g][1] + mem1[g][1] * c1) - (th1[g][1] - THRESH) * CO2;
            float dk1 = ((sp1bits >> (2 * g + 1)) & 1u) ? 0.f : DECAY;
            mem1[g][1] = mem1[g][1] * dk1 + h1v;
            if (mem1[g][1] > th1[g][1]) newsp1 |= 1u << (2 * g + 1);
        }
        __syncthreads();  // all gathers done before mask rewrite
        #pragma unroll
        for (int g = 0; g < 4; g++) {
            unsigned bl0 = __ballot_sync(0xffffffffu, (newsp1 >> (2 * g)) & 1u);
            if ((tid & 31) == 0) sp1m[g][tid >> 5] = bl0;
            unsigned bl1 = __ballot_sync(0xffffffffu, (newsp1 >> (2 * g + 1)) & 1u);
            if ((tid & 31) == 0) sp1m[g][8 + (tid >> 5)] = bl1;
        }
        sp1bits = newsp1;
        __syncthreads();

        // ================= layer 2 =================
        build_list(sp1m, lst, &s_cnt, tid);
        __syncthreads();
        cnt = s_cnt;
        #pragma unroll
        for (int g = 0; g < 4; g++) { acc0[g] = 0.f; acc1[g] = 0.f; }
        #pragma unroll 2
        for (int a = 0; a < cnt; a++) {
            unsigned e = lst[a];
            int j = (int)(e & 0xffffu);
            unsigned gm = e >> 16;
            const float* wr = &g_W2T[(size_t)j * H];
            float w0 = wr[tid], w1 = wr[tid + 256];
            #pragma unroll
            for (int g = 0; g < 4; g++)
                if (gm & (1u << g)) { acc0[g] += w0; acc1[g] += w1; }
        }
        unsigned newsp2 = 0;
        #pragma unroll
        for (int g = 0; g < 4; g++) {
            float h0 = acc0[g] + bias2a;
            float h1v = acc1[g] + bias2b;
            th2[g][0] = (th2[g][0] + mem2[g][0] * c0) - (th2[g][0] - THRESH) * CO2;
            float dk0 = ((sp2bits >> (2 * g)) & 1u) ? 0.f : DECAY;
            mem2[g][0] = mem2[g][0] * dk0 + h0;
            if (mem2[g][0] > th2[g][0]) newsp2 |= 1u << (2 * g);
            th2[g][1] = (th2[g][1] + mem2[g][1] * c1) - (th2[g][1] - THRESH) * CO2;
            float dk1 = ((sp2bits >> (2 * g + 1)) & 1u) ? 0.f : DECAY;
            mem2[g][1] = mem2[g][1] * dk1 + h1v;
            if (mem2[g][1] > th2[g][1]) newsp2 |= 1u << (2 * g + 1);
        }
        __syncthreads();
        #pragma unroll
        for (int g = 0; g < 4; g++) {
            unsigned bl0 = __ballot_sync(0xffffffffu, (newsp2 >> (2 * g)) & 1u);
            if ((tid & 31) == 0) sp2m[g][tid >> 5] = bl0;
            unsigned bl1 = __ballot_sync(0xffffffffu, (newsp2 >> (2 * g + 1)) & 1u);
            if ((tid & 31) == 0) sp2m[g][8 + (tid >> 5)] = bl1;
        }
        sp2bits = newsp2;
        __syncthreads();

        // ================= readout =================
        build_list(sp2m, lst, &s_cnt, tid);
        __syncthreads();
        cnt = s_cnt;
        if (odo) {
            for (int a = 0; a < cnt; a++) {
                unsigned e = lst[a];
                if ((e >> (16 + og)) & 1u)
                    oacc += g_WoT[(size_t)(e & 0xffffu) * OUTSZ + ok];
            }
        }
        __syncthreads(); // protect lst before next-iteration rebuild
    }

    if (odo)
        out[(size_t)(n0 + og) * OUTSZ + ok] = oacc / (float)T_STEPS + bo[ok];
}

// ------------ launch ------------
extern "C" void kernel_launch(void* const* d_in, const int* in_sizes, int n_in,
                              void* d_out, int out_size) {
    const float* input = (const float*)d_in[0];
    const float* w1    = (const float*)d_in[1];
    const float* b1    = (const float*)d_in[2];
    const float* wr    = (const float*)d_in[3];
    const float* br    = (const float*)d_in[4];
    const float* w2    = (const float*)d_in[5];
    const float* b2    = (const float*)d_in[6];
    const float* wo    = (const float*)d_in[7];
    const float* bo    = (const float*)d_in[8];
    const float* fre   = (const float*)d_in[9];
    float* out = (float*)d_out;

    k_ce<<<T_STEPS, H>>>(fre);
    k_transpose<<<dim3(16, 16), dim3(32, 8)>>>(wr, 0);
    k_transpose<<<dim3(16, 16), dim3(32, 8)>>>(w2, 1);
    k_wo<<<1, H>>>(wo);
    k_gemm_x1<<<dim3(H / BN, (T_STEPS * NBATCH) / BM), 256>>>(input, w1, b1, br);
    k_snn<<<NBATCH / 4, 256>>>(b2, bo, out);
}

// round 2
// speedup vs baseline: 1.2028x; 1.2028x over previous
#include <cuda_runtime.h>
#include <math.h>
#include <stdint.h>

#define T_STEPS 101
#define INSZ 700
#define H 512
#define OUTSZ 20
#define NBATCH 512
#define THRESH 0.5f
#define DECAY 0.5f
#define CO2 0.02f

// ------------ device scratch (static: no allocs allowed) ------------
__device__ float g_X1[(size_t)T_STEPS * NBATCH * H];   // precomputed input proj (+b1+br)
__device__ float g_WrT[H * H];                         // w_h2h1^T rows permuted to ballot order
__device__ float g_W2T[H * H];                         // w_i2h2^T rows permuted to ballot order
__device__ float g_WoT[H * OUTSZ];                     // w_h2o3^T rows permuted to ballot order
__device__ float g_ce[T_STEPS * H];                    // temporal encoding

// ballot-order permutation: neuron n -> list/bit position p
// thread tid owns neurons (2*tid, 2*tid+1); ballot bit p = 64*warp + 32*slot + lane
__host__ __device__ __forceinline__ int p_of(int n) {
    int w = n >> 6, s = n & 1, l = (n >> 1) & 31;
    return w * 64 + s * 32 + l;
}

// ------------ ce precompute ------------
__global__ void k_ce(const float* __restrict__ fre) {
    int i = threadIdx.x;     // 0..511
    int t = blockIdx.x;      // 0..100
    double dt_d = 0.1 / pow(100.0, (double)i / 512.0);
    float dtf = (float)dt_d;
    float fd  = fre[i] * dtf;          // fp32, matches (fre*dt) in reference
    float arg = fd * (float)t;         // fp32 product, matches broadcast multiply
    g_ce[t * H + i] = (float)cos((double)arg) * 0.1f;
}

// ------------ 512x512 transpose with row permutation: dst[p_of(j)][i] = src[i][j] ------------
__global__ void k_transpose(const float* __restrict__ src, int which) {
    __shared__ float tile[32][33];
    float* dst = (which == 0) ? g_WrT : g_W2T;
    int x  = blockIdx.x * 32 + threadIdx.x;
    int y0 = blockIdx.y * 32;
    for (int r = threadIdx.y; r < 32; r += 8)
        tile[r][threadIdx.x] = src[(size_t)(y0 + r) * H + x];
    __syncthreads();
    int xo  = blockIdx.y * 32 + threadIdx.x;
    for (int r = threadIdx.y; r < 32; r += 8) {
        int j = blockIdx.x * 32 + r;          // original column index (presyn neuron)
        dst[(size_t)p_of(j) * H + xo] = tile[threadIdx.x][r];
    }
}

// ------------ readout weight transpose (permuted rows) ------------
__global__ void k_wo(const float* __restrict__ wo) {
    int j = threadIdx.x; // 0..511
    int p = p_of(j);
    for (int k = 0; k < OUTSZ; k++)
        g_WoT[p * OUTSZ + k] = wo[k * H + j];
}

// ------------ X1 GEMM: 128x128x8 double-buffered, 8x8 micro-tile ------------
#define BM 128
#define BN 128
#define BK 8
#define NIT ((INSZ + BK - 1) / BK)   // 88

__device__ __forceinline__ float4 ld4g(const float* __restrict__ p, int k) {
    if (k + 3 < INSZ) return *(const float4*)(p + k);
    float4 v;
    v.x = (k + 0 < INSZ) ? p[k + 0] : 0.f;
    v.y = (k + 1 < INSZ) ? p[k + 1] : 0.f;
    v.z = (k + 2 < INSZ) ? p[k + 2] : 0.f;
    v.w = (k + 3 < INSZ) ? p[k + 3] : 0.f;
    return v;
}

__global__ __launch_bounds__(256) void k_gemm_x1(
    const float* __restrict__ A,   // input  [51712 x 700]
    const float* __restrict__ B,   // w_i2h1 [512 x 700]
    const float* __restrict__ b1,
    const float* __restrict__ br)
{
    __shared__ float As[2][BK][BM];
    __shared__ float Bs[2][BK][BN];
    int tid = threadIdx.x;
    int m0 = blockIdx.y * BM, n0 = blockIdx.x * BN;
    int ty = tid >> 4, tx = tid & 15;

    int lr  = tid >> 1;          // load row 0..127
    int lk4 = (tid & 1) * 4;     // k offset within tile (0 or 4)
    const float* Aptr = A + (size_t)(m0 + lr) * INSZ;
    const float* Bptr = B + (size_t)(n0 + lr) * INSZ;

    float acc[8][8];
    #pragma unroll
    for (int i = 0; i < 8; i++)
        #pragma unroll
        for (int j = 0; j < 8; j++) acc[i][j] = 0.f;

    // prologue load
    {
        float4 av = ld4g(Aptr, lk4);
        float4 bv = ld4g(Bptr, lk4);
        As[0][lk4 + 0][lr] = av.x; As[0][lk4 + 1][lr] = av.y;
        As[0][lk4 + 2][lr] = av.z; As[0][lk4 + 3][lr] = av.w;
        Bs[0][lk4 + 0][lr] = bv.x; Bs[0][lk4 + 1][lr] = bv.y;
        Bs[0][lk4 + 2][lr] = bv.z; Bs[0][lk4 + 3][lr] = bv.w;
    }
    __syncthreads();

    for (int it = 0; it < NIT; it++) {
        int buf = it & 1;
        if (it + 1 < NIT) {
            int k0 = (it + 1) * BK;
            float4 av = ld4g(Aptr, k0 + lk4);
            float4 bv = ld4g(Bptr, k0 + lk4);
            As[buf ^ 1][lk4 + 0][lr] = av.x; As[buf ^ 1][lk4 + 1][lr] = av.y;
            As[buf ^ 1][lk4 + 2][lr] = av.z; As[buf ^ 1][lk4 + 3][lr] = av.w;
            Bs[buf ^ 1][lk4 + 0][lr] = bv.x; Bs[buf ^ 1][lk4 + 1][lr] = bv.y;
            Bs[buf ^ 1][lk4 + 2][lr] = bv.z; Bs[buf ^ 1][lk4 + 3][lr] = bv.w;
        }
        #pragma unroll
        for (int k = 0; k < BK; k++) {
            float a8[8], b8[8];
            *(float4*)&a8[0] = *(const float4*)&As[buf][k][ty * 8];
            *(float4*)&a8[4] = *(const float4*)&As[buf][k][ty * 8 + 4];
            *(float4*)&b8[0] = *(const float4*)&Bs[buf][k][tx * 8];
            *(float4*)&b8[4] = *(const float4*)&Bs[buf][k][tx * 8 + 4];
            #pragma unroll
            for (int i = 0; i < 8; i++)
                #pragma unroll
                for (int j = 0; j < 8; j++)
                    acc[i][j] += a8[i] * b8[j];
        }
        __syncthreads();
    }

    float bs[8];
    #pragma unroll
    for (int j = 0; j < 8; j++) {
        int n = n0 + tx * 8 + j;
        bs[j] = b1[n] + br[n];
    }
    #pragma unroll
    for (int i = 0; i < 8; i++) {
        int m = m0 + ty * 8 + i;
        float* op = &g_X1[(size_t)m * H + n0 + tx * 8];
        float4 v0, v1;
        v0.x = acc[i][0] + bs[0]; v0.y = acc[i][1] + bs[1];
        v0.z = acc[i][2] + bs[2]; v0.w = acc[i][3] + bs[3];
        v1.x = acc[i][4] + bs[4]; v1.y = acc[i][5] + bs[5];
        v1.z = acc[i][6] + bs[6]; v1.w = acc[i][7] + bs[7];
        *(float4*)op = v0;
        *(float4*)(op + 4) = v1;
    }
}

// ------------ active-list compaction: union of 4 sample masks -> (p | gmask<<16) ------------
__device__ __forceinline__ void build_list(unsigned (*msk)[16], unsigned* lst, int* cnt, int tid) {
    if (tid < 32) {
        unsigned u = 0, g0 = 0, g1 = 0, g2 = 0, g3 = 0;
        if (tid < 16) {
            g0 = msk[0][tid]; g1 = msk[1][tid]; g2 = msk[2][tid]; g3 = msk[3][tid];
            u = g0 | g1 | g2 | g3;
        }
        int c = __popc(u);
        int off = c;
        #pragma unroll
        for (int d = 1; d < 32; d <<= 1) {
            int v = __shfl_up_sync(0xffffffffu, off, d);
            if (tid >= d) off += v;
        }
        off -= c;                    // exclusive prefix
        if (tid == 31) *cnt = off;   // lane31 has c=0 -> exclusive == total
        unsigned uu = u;
        while (uu) {
            int b = __ffs(uu) - 1;
            uu &= uu - 1;
            unsigned gm = ((g0 >> b) & 1u) | (((g1 >> b) & 1u) << 1)
                        | (((g2 >> b) & 1u) << 2) | (((g3 >> b) & 1u) << 3);
            lst[off++] = (unsigned)(tid * 32 + b) | (gm << 16);
        }
    }
}

// accumulate one list entry (float2 weight row slice) into per-sample accumulators
#define ACCUM(e, v)                                                       \
    do {                                                                  \
        if ((e) & 0x10000u) { a0x += (v).x; a0y += (v).y; }               \
        if ((e) & 0x20000u) { a1x += (v).x; a1y += (v).y; }               \
        if ((e) & 0x40000u) { a2x += (v).x; a2y += (v).y; }               \
        if ((e) & 0x80000u) { a3x += (v).x; a3y += (v).y; }               \
    } while (0)

// ------------ sequential SNN: 128 CTAs x 4 samples, 256 threads, 2 adjacent neurons/thread ----
__global__ __launch_bounds__(256) void k_snn(
    const float* __restrict__ b2,
    const float* __restrict__ bo,
    float* __restrict__ out)
{
    int tid = threadIdx.x;
    int n0  = blockIdx.x * 4;
    int wi  = tid >> 5;          // warp index
    int lane = tid & 31;

    __shared__ unsigned sp1m[4][16];
    __shared__ unsigned sp2m[4][16];
    __shared__ unsigned lst[512];
    __shared__ int s_cnt;

    // slot 0 = neuron 2*tid, slot 1 = neuron 2*tid+1
    float mem1[4][2], th1[4][2], mem2[4][2], th2[4][2];
    #pragma unroll
    for (int g = 0; g < 4; g++) {
        mem1[g][0] = mem1[g][1] = 0.f;
        mem2[g][0] = mem2[g][1] = 0.f;
        th1[g][0] = th1[g][1] = THRESH;
        th2[g][0] = th2[g][1] = THRESH;
    }
    unsigned sp1bits = 0, sp2bits = 0; // bit (2g+slot)
    float oacc = 0.f;
    int og = tid / OUTSZ, ok = tid % OUTSZ;
    bool odo = (tid < 4 * OUTSZ);

    if (tid < 16) {
        #pragma unroll
        for (int g = 0; g < 4; g++) { sp1m[g][tid] = 0u; sp2m[g][tid] = 0u; }
    }
    __syncthreads();

    float2 b2v = *(const float2*)&b2[2 * tid];
    const float2* Wr2 = (const float2*)g_WrT;
    const float2* W22 = (const float2*)g_W2T;

    for (int t = 0; t < T_STEPS; t++) {
        float2 c01 = *(const float2*)&g_ce[t * H + 2 * tid];

        // ================= layer 1 =================
        build_list(sp1m, lst, &s_cnt, tid);
        __syncthreads();
        int cnt = s_cnt;
        float a0x = 0.f, a0y = 0.f, a1x = 0.f, a1y = 0.f;
        float a2x = 0.f, a2y = 0.f, a3x = 0.f, a3y = 0.f;
        {
            int a = 0;
            for (; a + 4 <= cnt; a += 4) {
                unsigned e0 = lst[a], e1 = lst[a + 1], e2 = lst[a + 2], e3 = lst[a + 3];
                float2 v0 = Wr2[((e0 & 0xffffu) << 8) + tid];
                float2 v1 = Wr2[((e1 & 0xffffu) << 8) + tid];
                float2 v2 = Wr2[((e2 & 0xffffu) << 8) + tid];
                float2 v3 = Wr2[((e3 & 0xffffu) << 8) + tid];
                ACCUM(e0, v0); ACCUM(e1, v1); ACCUM(e2, v2); ACCUM(e3, v3);
            }
            for (; a < cnt; a++) {
                unsigned e = lst[a];
                float2 v = Wr2[((e & 0xffffu) << 8) + tid];
                ACCUM(e, v);
            }
        }
        unsigned newsp1 = 0;
        {
            float accx[4] = {a0x, a1x, a2x, a3x};
            float accy[4] = {a0y, a1y, a2y, a3y};
            #pragma unroll
            for (int g = 0; g < 4; g++) {
                const float2 x01 = *(const float2*)&g_X1[((size_t)t * NBATCH + n0 + g) * H + 2 * tid];
                float h0 = x01.x + accx[g];
                float h1v = x01.y + accy[g];
                th1[g][0] = (th1[g][0] + mem1[g][0] * c01.x) - (th1[g][0] - THRESH) * CO2;
                float dk0 = ((sp1bits >> (2 * g)) & 1u) ? 0.f : DECAY;
                mem1[g][0] = mem1[g][0] * dk0 + h0;
                if (mem1[g][0] > th1[g][0]) newsp1 |= 1u << (2 * g);
                th1[g][1] = (th1[g][1] + mem1[g][1] * c01.y) - (th1[g][1] - THRESH) * CO2;
                float dk1 = ((sp1bits >> (2 * g + 1)) & 1u) ? 0.f : DECAY;
                mem1[g][1] = mem1[g][1] * dk1 + h1v;
                if (mem1[g][1] > th1[g][1]) newsp1 |= 1u << (2 * g + 1);
            }
        }
        __syncthreads();  // all gathers done before mask rewrite
        #pragma unroll
        for (int g = 0; g < 4; g++) {
            unsigned bl0 = __ballot_sync(0xffffffffu, (newsp1 >> (2 * g)) & 1u);
            unsigned bl1 = __ballot_sync(0xffffffffu, (newsp1 >> (2 * g + 1)) & 1u);
            if (lane == 0) { sp1m[g][2 * wi] = bl0; sp1m[g][2 * wi + 1] = bl1; }
        }
        sp1bits = newsp1;
        __syncthreads();

        // ================= layer 2 =================
        build_list(sp1m, lst, &s_cnt, tid);
        __syncthreads();
        cnt = s_cnt;
        a0x = a0y = a1x = a1y = a2x = a2y = a3x = a3y = 0.f;
        {
            int a = 0;
            for (; a + 4 <= cnt; a += 4) {
                unsigned e0 = lst[a], e1 = lst[a + 1], e2 = lst[a + 2], e3 = lst[a + 3];
                float2 v0 = W22[((e0 & 0xffffu) << 8) + tid];
                float2 v1 = W22[((e1 & 0xffffu) << 8) + tid];
                float2 v2 = W22[((e2 & 0xffffu) << 8) + tid];
                float2 v3 = W22[((e3 & 0xffffu) << 8) + tid];
                ACCUM(e0, v0); ACCUM(e1, v1); ACCUM(e2, v2); ACCUM(e3, v3);
            }
            for (; a < cnt; a++) {
                unsigned e = lst[a];
                float2 v = W22[((e & 0xffffu) << 8) + tid];
                ACCUM(e, v);
            }
        }
        unsigned newsp2 = 0;
        {
            float accx[4] = {a0x, a1x, a2x, a3x};
            float accy[4] = {a0y, a1y, a2y, a3y};
            #pragma unroll
            for (int g = 0; g < 4; g++) {
                float h0 = accx[g] + b2v.x;
                float h1v = accy[g] + b2v.y;
                th2[g][0] = (th2[g][0] + mem2[g][0] * c01.x) - (th2[g][0] - THRESH) * CO2;
                float dk0 = ((sp2bits >> (2 * g)) & 1u) ? 0.f : DECAY;
                mem2[g][0] = mem2[g][0] * dk0 + h0;
                if (mem2[g][0] > th2[g][0]) newsp2 |= 1u << (2 * g);
                th2[g][1] = (th2[g][1] + mem2[g][1] * c01.y) - (th2[g][1] - THRESH) * CO2;
                float dk1 = ((sp2bits >> (2 * g + 1)) & 1u) ? 0.f : DECAY;
                mem2[g][1] = mem2[g][1] * dk1 + h1v;
                if (mem2[g][1] > th2[g][1]) newsp2 |= 1u << (2 * g + 1);
            }
        }
        __syncthreads();
        #pragma unroll
        for (int g = 0; g < 4; g++) {
            unsigned bl0 = __ballot_sync(0xffffffffu, (newsp2 >> (2 * g)) & 1u);
            unsigned bl1 = __ballot_sync(0xffffffffu, (newsp2 >> (2 * g + 1)) & 1u);
            if (lane == 0) { sp2m[g][2 * wi] = bl0; sp2m[g][2 * wi + 1] = bl1; }
        }
        sp2bits = newsp2;
        __syncthreads();

        // ================= readout =================
        build_list(sp2m, lst, &s_cnt, tid);
        __syncthreads();
        cnt = s_cnt;
        if (odo) {
            for (int a = 0; a < cnt; a++) {
                unsigned e = lst[a];
                if ((e >> (16 + og)) & 1u)
                    oacc += g_WoT[(size_t)(e & 0xffffu) * OUTSZ + ok];
            }
        }
        __syncthreads(); // protect lst before next-iteration rebuild
    }

    if (odo)
        out[(size_t)(n0 + og) * OUTSZ + ok] = oacc / (float)T_STEPS + bo[ok];
}

// ------------ launch ------------
extern "C" void kernel_launch(void* const* d_in, const int* in_sizes, int n_in,
                              void* d_out, int out_size) {
    const float* input = (const float*)d_in[0];
    const float* w1    = (const float*)d_in[1];
    const float* b1    = (const float*)d_in[2];
    const float* wr    = (const float*)d_in[3];
    const float* br    = (const float*)d_in[4];
    const float* w2    = (const float*)d_in[5];
    const float* b2    = (const float*)d_in[6];
    const float* wo    = (const float*)d_in[7];
    const float* bo    = (const float*)d_in[8];
    const float* fre   = (const float*)d_in[9];
    float* out = (float*)d_out;

    k_ce<<<T_STEPS, H>>>(fre);
    k_transpose<<<dim3(16, 16), dim3(32, 8)>>>(wr, 0);
    k_transpose<<<dim3(16, 16), dim3(32, 8)>>>(w2, 1);
    k_wo<<<1, H>>>(wo);
    k_gemm_x1<<<dim3(H / BN, (T_STEPS * NBATCH) / BM), 256>>>(input, w1, b1, br);
    k_snn<<<NBATCH / 4, 256>>>(b2, bo, out);
}